// round 6
// baseline (speedup 1.0000x reference)
#include <cuda_runtime.h>

// ---------------------------------------------------------------------------
// SSIM (5x5 Gaussian, sigma=1.5, SAME zero padding), fused single kernel.
// R6: convolve (s,d)=(a+b,a-b) and (s^2,d^2) -- 4 fields instead of 5.
//     a^2+b^2 = (s^2+d^2)/2, ab = (s^2-d^2)/4 recovered in the epilogue.
// Separable conv + f32x2 packed math + register rolling window +
// one-row software-pipelined global prefetch. 5 CTAs/SM pinned.
// ---------------------------------------------------------------------------

constexpr int W    = 512;
constexpr int H    = 512;
constexpr int C    = 3;
constexpr int NB   = 16;
constexpr int BX   = 128;   // output columns per block (4 warps x 32)
constexpr int ROWS = 32;    // output rows per block

__device__ __forceinline__ unsigned long long pk2(float lo, float hi) {
    unsigned long long r;
    asm("mov.b64 %0, {%1, %2};" : "=l"(r) : "f"(lo), "f"(hi));
    return r;
}
__device__ __forceinline__ void up2(unsigned long long v, float& lo, float& hi) {
    asm("mov.b64 {%0, %1}, %2;" : "=f"(lo), "=f"(hi) : "l"(v));
}
__device__ __forceinline__ unsigned long long fma2_(unsigned long long a,
                                                    unsigned long long b,
                                                    unsigned long long c) {
    unsigned long long d;
    asm("fma.rn.f32x2 %0, %1, %2, %3;" : "=l"(d) : "l"(a), "l"(b), "l"(c));
    return d;
}
__device__ __forceinline__ unsigned long long mul2_(unsigned long long a,
                                                    unsigned long long b) {
    unsigned long long d;
    asm("mul.rn.f32x2 %0, %1, %2;" : "=l"(d) : "l"(a), "l"(b));
    return d;
}

__global__ __launch_bounds__(128, 5)
void ssim_kernel(const float* __restrict__ img1,
                 const float* __restrict__ img2,
                 const float* __restrict__ win,
                 float* __restrict__ out)
{
    // Per-warp row buffer (36 cols = 32 + 4 halo): (s,d) pairs.
    __shared__ float2 sSD[4][C][36];

    const int lane = threadIdx.x & 31;
    const int warp = threadIdx.x >> 5;
    const int b    = blockIdx.z;
    const int y0   = blockIdx.y * ROWS;
    const int x0   = blockIdx.x * BX + warp * 32;
    const int xo   = x0 + lane;
    const int gx   = x0 - 2 + lane;       // main halo col
    const int gx2  = x0 + 30 + lane;      // extra halo col (lane<4)

    // Recover separable 1D Gaussian: g[j] = w2d[2][j] / sqrt(w2d[2][2])
    const float gc = sqrtf(win[12]);
    unsigned long long wg[5];
#pragma unroll
    for (int j = 0; j < 5; ++j) {
        const float gj = __fdividef(win[10 + j], gc);
        wg[j] = pk2(gj, gj);
    }

    const bool gxok  = (gx >= 0) && (gx < W);
    const bool gx2ok = (lane < 4) && (gx2 < W);

    int cbase[C];
#pragma unroll
    for (int c = 0; c < C; ++c) cbase[c] = ((b * C + c) * H) * W;

    // Rolling horizontal-filtered state: 5 row slots per channel.
    unsigned long long hSD[C][5], hSQ[C][5];

    // Prefetch registers (row s, loaded one iteration ahead): raw a,b.
    float pa[C], pb[C], qa[C], qb[C];

    // Prologue: prefetch row step 0 (r = y0-2).
    {
        const int r = y0 - 2;
        const bool rok = (r >= 0);
        const int rclamp = (rok ? r : 0) * W;
        float ta[C], tb[C], ua[C], ub[C];
#pragma unroll
        for (int c = 0; c < C; ++c) {
            const int off = cbase[c] + rclamp;
            ta[c] = gxok  ? img1[off + gx]  : 0.0f;
            tb[c] = gxok  ? img2[off + gx]  : 0.0f;
            ua[c] = gx2ok ? img1[off + gx2] : 0.0f;
            ub[c] = gx2ok ? img2[off + gx2] : 0.0f;
        }
#pragma unroll
        for (int c = 0; c < C; ++c) {
            pa[c] = rok ? ta[c] : 0.0f;
            pb[c] = rok ? tb[c] : 0.0f;
            qa[c] = rok ? ua[c] : 0.0f;
            qb[c] = rok ? ub[c] : 0.0f;
        }
    }

    const float C1 = 0.0001f;  // (0.01)^2
    const float C2 = 0.0009f;  // (0.03)^2

    for (int base = 0; base < ROWS + 8; base += 5) {
#pragma unroll
        for (int k = 0; k < 5; ++k) {
            const int s = base + k;
            if (s < ROWS + 4) {
                // ---- store prefetched row as (s,d) = (a+b, a-b) ----
                __syncwarp();
#pragma unroll
                for (int c = 0; c < C; ++c) {
                    sSD[warp][c][lane] =
                        make_float2(pa[c] + pb[c], pa[c] - pb[c]);
                    if (lane < 4)
                        sSD[warp][c][32 + lane] =
                            make_float2(qa[c] + qb[c], qa[c] - qb[c]);
                }
                __syncwarp();

                // ---- prefetch next row (hidden behind compute below) ----
                {
                    const int r = y0 - 1 + s;          // (y0-2) + (s+1)
                    const bool rok = (r >= 0) && (r < H);
                    const int rclamp = (rok ? r : 0) * W;
                    float ta[C], tb[C], ua[C], ub[C];
#pragma unroll
                    for (int c = 0; c < C; ++c) {
                        const int off = cbase[c] + rclamp;
                        ta[c] = gxok  ? img1[off + gx]  : 0.0f;
                        tb[c] = gxok  ? img2[off + gx]  : 0.0f;
                        ua[c] = gx2ok ? img1[off + gx2] : 0.0f;
                        ub[c] = gx2ok ? img2[off + gx2] : 0.0f;
                    }
#pragma unroll
                    for (int c = 0; c < C; ++c) {
                        pa[c] = rok ? ta[c] : 0.0f;
                        pb[c] = rok ? tb[c] : 0.0f;
                        qa[c] = rok ? ua[c] : 0.0f;
                        qb[c] = rok ? ub[c] : 0.0f;
                    }
                }

                // ---- horizontal 5-tap pass into slot k ----
                // 1 LDS.64 + 3 fma-pipe ops per tap.
#pragma unroll
                for (int c = 0; c < C; ++c) {
                    const unsigned long long* pSD =
                        (const unsigned long long*)&sSD[warp][c][0];
                    unsigned long long ssd = 0ull, ssq = 0ull;
#pragma unroll
                    for (int t = 0; t < 5; ++t) {
                        const unsigned long long pp = pSD[lane + t];
                        ssd = fma2_(pp, wg[t], ssd);              // s, d
                        ssq = fma2_(mul2_(pp, pp), wg[t], ssq);   // s2, d2
                    }
                    hSD[c][k] = ssd; hSQ[c][k] = ssq;
                }

                // ---- vertical 5-tap pass + epilogue for row y0+s-4 ----
                if (s >= 4) {
                    float num[C], den[C];
#pragma unroll
                    for (int c = 0; c < C; ++c) {
                        unsigned long long vsd = 0ull, vsq = 0ull;
#pragma unroll
                        for (int j = 0; j < 5; ++j) {
                            const int slot = (k + 1 + j) % 5;  // row s-4+j
                            vsd = fma2_(hSD[c][slot], wg[j], vsd);
                            vsq = fma2_(hSQ[c][slot], wg[j], vsq);
                        }
                        float cs, cd, css, csd;
                        up2(vsd, cs, cd);     // conv(s), conv(d)
                        up2(vsq, css, csd);   // conv(s^2), conv(d^2)
                        const float cs2 = cs * cs;
                        const float cd2 = cd * cd;
                        // mu1*mu2 = (cs^2 - cd^2)/4 ; mu1^2+mu2^2 = (cs^2+cd^2)/2
                        const float m12 = (cs2 - cd2) * 0.25f;
                        const float msq = (cs2 + cd2) * 0.5f;
                        // conv(ab) = (css - csd)/4 ; conv(a^2)+conv(b^2) = (css+csd)/2
                        const float cab = (css - csd) * 0.25f;
                        const float csum = (css + csd) * 0.5f;
                        const float s12  = cab - m12;    // sigma12
                        const float svar = csum - msq;   // sigma1^2 + sigma2^2
                        num[c] = (2.0f * m12 + C1) * (2.0f * s12 + C2);
                        den[c] = (msq + C1) * (svar + C2);
                    }
                    // Sum of 3 ratios with a single division.
                    const float d01   = den[0] * den[1];
                    const float denom = d01 * den[2];
                    float numer = num[2] * d01;
                    numer = fmaf(num[0], den[1] * den[2], numer);
                    numer = fmaf(num[1], den[0] * den[2], numer);
                    const int y = y0 + s - 4;
                    out[(b * H + y) * W + xo] =
                        __fdividef(numer, denom) * (1.0f / 3.0f);
                }
            }
        }
    }
}

extern "C" void kernel_launch(void* const* d_in, const int* in_sizes, int n_in,
                              void* d_out, int out_size)
{
    const float* img1 = (const float*)d_in[0];
    const float* img2 = (const float*)d_in[1];
    const float* win  = (const float*)d_in[2];
    float* out = (float*)d_out;

    dim3 grid(W / BX, H / ROWS, NB);  // (4, 16, 16) = 1024 blocks
    ssim_kernel<<<grid, 128>>>(img1, img2, win, out);
}

// round 8
// speedup vs baseline: 1.0101x; 1.0101x over previous
#include <cuda_runtime.h>

// ---------------------------------------------------------------------------
// SSIM (5x5 Gaussian, sigma=1.5, SAME zero padding), fused single kernel.
// R8: two rows per iteration (R7 structure) with the ring hazard fixed:
//     row s1's horizontal result is committed to the 5-slot ring only AFTER
//     the s0 epilogue has consumed slot (s0-4)%5 == s1%5.
// ---------------------------------------------------------------------------

constexpr int W    = 512;
constexpr int H    = 512;
constexpr int C    = 3;
constexpr int NB   = 16;
constexpr int BX   = 128;   // output columns per block (4 warps x 32)
constexpr int ROWS = 32;    // output rows per block
constexpr int STEPS = ROWS + 4;   // 36 input rows per block

__device__ __forceinline__ unsigned long long pk2(float lo, float hi) {
    unsigned long long r;
    asm("mov.b64 %0, {%1, %2};" : "=l"(r) : "f"(lo), "f"(hi));
    return r;
}
__device__ __forceinline__ void up2(unsigned long long v, float& lo, float& hi) {
    asm("mov.b64 {%0, %1}, %2;" : "=f"(lo), "=f"(hi) : "l"(v));
}
__device__ __forceinline__ unsigned long long fma2_(unsigned long long a,
                                                    unsigned long long b,
                                                    unsigned long long c) {
    unsigned long long d;
    asm("fma.rn.f32x2 %0, %1, %2, %3;" : "=l"(d) : "l"(a), "l"(b), "l"(c));
    return d;
}
__device__ __forceinline__ unsigned long long mul2_(unsigned long long a,
                                                    unsigned long long b) {
    unsigned long long d;
    asm("mul.rn.f32x2 %0, %1, %2;" : "=l"(d) : "l"(a), "l"(b));
    return d;
}

// Load one input row (all channels, both images) into prefetch registers.
__device__ __forceinline__ void load_row(
    const float* __restrict__ img1, const float* __restrict__ img2,
    const int* cbase, int r, int gx, int gx2, bool gxok, bool gx2ok,
    float* pa, float* pb, float* qa, float* qb)
{
    const bool rok = (r >= 0) && (r < H);
    const int rclamp = (rok ? r : 0) * W;
    float ta[C], tb[C], ua[C], ub[C];
#pragma unroll
    for (int c = 0; c < C; ++c) {
        const int off = cbase[c] + rclamp;
        ta[c] = gxok  ? img1[off + gx]  : 0.0f;
        tb[c] = gxok  ? img2[off + gx]  : 0.0f;
        ua[c] = gx2ok ? img1[off + gx2] : 0.0f;
        ub[c] = gx2ok ? img2[off + gx2] : 0.0f;
    }
#pragma unroll
    for (int c = 0; c < C; ++c) {
        pa[c] = rok ? ta[c] : 0.0f;
        pb[c] = rok ? tb[c] : 0.0f;
        qa[c] = rok ? ua[c] : 0.0f;
        qb[c] = rok ? ub[c] : 0.0f;
    }
}

__global__ __launch_bounds__(128, 4)
void ssim_kernel(const float* __restrict__ img1,
                 const float* __restrict__ img2,
                 const float* __restrict__ win,
                 float* __restrict__ out)
{
    // Per-warp double row buffer (even/odd step), (s,d) pairs, 36 cols.
    __shared__ float2 sSD[4][2][C][36];

    const int lane = threadIdx.x & 31;
    const int warp = threadIdx.x >> 5;
    const int b    = blockIdx.z;
    const int y0   = blockIdx.y * ROWS;
    const int x0   = blockIdx.x * BX + warp * 32;
    const int xo   = x0 + lane;
    const int gx   = x0 - 2 + lane;       // main halo col
    const int gx2  = x0 + 30 + lane;      // extra halo col (lane<4)

    // Recover separable 1D Gaussian: g[j] = w2d[2][j] / sqrt(w2d[2][2])
    const float gc = sqrtf(win[12]);
    unsigned long long wg[5];
#pragma unroll
    for (int j = 0; j < 5; ++j) {
        const float gj = __fdividef(win[10 + j], gc);
        wg[j] = pk2(gj, gj);
    }

    const bool gxok  = (gx >= 0) && (gx < W);
    const bool gx2ok = (lane < 4) && (gx2 < W);

    int cbase[C];
#pragma unroll
    for (int c = 0; c < C; ++c) cbase[c] = ((b * C + c) * H) * W;

    // Rolling horizontal-filtered state: 5 row slots per channel.
    unsigned long long hSD[C][5], hSQ[C][5];

    // Two-row prefetch registers (rows s0, s1 of the current pair).
    float paA[C], pbA[C], qaA[C], qbA[C];
    float paB[C], pbB[C], qaB[C], qbB[C];

    // Prologue: prefetch rows for steps 0 and 1 (r = y0-2, y0-1).
    load_row(img1, img2, cbase, y0 - 2, gx, gx2, gxok, gx2ok, paA, pbA, qaA, qbA);
    load_row(img1, img2, cbase, y0 - 1, gx, gx2, gxok, gx2ok, paB, pbB, qaB, qbB);

    const float C1 = 0.0001f;  // (0.01)^2
    const float C2 = 0.0009f;  // (0.03)^2

    // SSIM epilogue for output step se (slot indices static when se static).
    auto epilogue = [&](int se) {
        float num[C], den[C];
#pragma unroll
        for (int c = 0; c < C; ++c) {
            unsigned long long vsd = 0ull, vsq = 0ull;
#pragma unroll
            for (int j = 0; j < 5; ++j) {
                const int slot = (se + 1 + j) % 5;  // row se-4+j
                vsd = fma2_(hSD[c][slot], wg[j], vsd);
                vsq = fma2_(hSQ[c][slot], wg[j], vsq);
            }
            float cs, cd, css, csd;
            up2(vsd, cs, cd);     // conv(s), conv(d)
            up2(vsq, css, csd);   // conv(s^2), conv(d^2)
            const float cs2 = cs * cs;
            const float cd2 = cd * cd;
            const float m12 = (cs2 - cd2) * 0.25f;   // mu1*mu2
            const float msq = (cs2 + cd2) * 0.5f;    // mu1^2+mu2^2
            const float cab = (css - csd) * 0.25f;   // conv(ab)
            const float csum = (css + csd) * 0.5f;   // conv(a2)+conv(b2)
            const float s12  = cab - m12;            // sigma12
            const float svar = csum - msq;           // sigma1^2+sigma2^2
            num[c] = (2.0f * m12 + C1) * (2.0f * s12 + C2);
            den[c] = (msq + C1) * (svar + C2);
        }
        const float d01   = den[0] * den[1];
        const float denom = d01 * den[2];
        float numer = num[2] * d01;
        numer = fmaf(num[0], den[1] * den[2], numer);
        numer = fmaf(num[1], den[0] * den[2], numer);
        const int y = y0 + se - 4;
        out[(b * H + y) * W + xo] = __fdividef(numer, denom) * (1.0f / 3.0f);
    };

    // Pair loop: 18 pairs; unroll 5 pairs (10 steps) so slot indices
    // (mod 5) are compile-time static (base % 10 == 0).
    for (int base = 0; base < STEPS; base += 10) {
#pragma unroll
        for (int kk = 0; kk < 5; ++kk) {
            const int s0 = base + 2 * kk;
            const int s1 = s0 + 1;
            if (s0 < STEPS) {
                // ---- store both prefetched rows as (s,d) ----
                __syncwarp();
#pragma unroll
                for (int c = 0; c < C; ++c) {
                    sSD[warp][0][c][lane] =
                        make_float2(paA[c] + pbA[c], paA[c] - pbA[c]);
                    sSD[warp][1][c][lane] =
                        make_float2(paB[c] + pbB[c], paB[c] - pbB[c]);
                    if (lane < 4) {
                        sSD[warp][0][c][32 + lane] =
                            make_float2(qaA[c] + qbA[c], qaA[c] - qbA[c]);
                        sSD[warp][1][c][32 + lane] =
                            make_float2(qaB[c] + qbB[c], qaB[c] - qbB[c]);
                    }
                }
                __syncwarp();

                // ---- prefetch next pair (rows s0+2, s1+2); 24 LDGs in
                //      flight, consumed only at the next iteration ----
                load_row(img1, img2, cbase, y0 - 2 + s0 + 2,
                         gx, gx2, gxok, gx2ok, paA, pbA, qaA, qbA);
                load_row(img1, img2, cbase, y0 - 2 + s1 + 2,
                         gx, gx2, gxok, gx2ok, paB, pbB, qaB, qbB);

                // ---- horizontal 5-tap pass for both rows (independent).
                //      Row s0 commits to the ring; row s1 stays in temps
                //      until the s0 epilogue has read slot (s0-4)%5==s1%5. ----
                unsigned long long tSD1[C], tSQ1[C];
#pragma unroll
                for (int c = 0; c < C; ++c) {
                    const unsigned long long* p0 =
                        (const unsigned long long*)&sSD[warp][0][c][0];
                    const unsigned long long* p1 =
                        (const unsigned long long*)&sSD[warp][1][c][0];
                    unsigned long long sd0 = 0ull, sq0 = 0ull;
                    unsigned long long sd1 = 0ull, sq1 = 0ull;
#pragma unroll
                    for (int t = 0; t < 5; ++t) {
                        const unsigned long long v0 = p0[lane + t];
                        const unsigned long long v1 = p1[lane + t];
                        sd0 = fma2_(v0, wg[t], sd0);
                        sq0 = fma2_(mul2_(v0, v0), wg[t], sq0);
                        sd1 = fma2_(v1, wg[t], sd1);
                        sq1 = fma2_(mul2_(v1, v1), wg[t], sq1);
                    }
                    hSD[c][s0 % 5] = sd0; hSQ[c][s0 % 5] = sq0;
                    tSD1[c] = sd1; tSQ1[c] = sq1;
                }

                // ---- epilogue for output row s0 (ring intact) ----
                if (s0 >= 4) epilogue(s0);

                // ---- commit row s1 into the ring, then its epilogue ----
#pragma unroll
                for (int c = 0; c < C; ++c) {
                    hSD[c][s1 % 5] = tSD1[c];
                    hSQ[c][s1 % 5] = tSQ1[c];
                }
                if (s1 >= 4) epilogue(s1);
            }
        }
    }
}

extern "C" void kernel_launch(void* const* d_in, const int* in_sizes, int n_in,
                              void* d_out, int out_size)
{
    const float* img1 = (const float*)d_in[0];
    const float* img2 = (const float*)d_in[1];
    const float* win  = (const float*)d_in[2];
    float* out = (float*)d_out;

    dim3 grid(W / BX, H / ROWS, NB);  // (4, 16, 16) = 1024 blocks
    ssim_kernel<<<grid, 128>>>(img1, img2, win, out);
}